// round 14
// baseline (speedup 1.0000x reference)
#include <cuda_runtime.h>
#include <cuda_bf16.h>
#include <cuda_fp16.h>
#include <cstdint>

#define N_ENT   30000
#define N_RELS  12
#define N_BASES 8
#define KGD     128
#define TOKD    768
#define BATCH   32
#define NCTX    50
#define SEQL    256
#define NEDGE   400000
#define MROWS   (BATCH * SEQL)   // 8192

// ---------------- scratch (__device__ globals; no allocations allowed) ----
__device__ __align__(256) __nv_bfloat16 g_wbf[N_RELS * N_ENT * KGD]; // 92 MB bf16 weights
__device__ float g_kg[N_ENT * KGD];                 // kg_embedding
__device__ int   g_cnt[N_RELS * N_ENT];             // per (rel,dst) edge counts
__device__ __align__(16) int g_deg[N_ENT];          // per-dst degree
__device__ __align__(16) int g_off[N_ENT + 4];      // exclusive scan of degree
__device__ int   g_pos[N_ENT];                      // running placement counters
__device__ uint32_t g_sorted[NEDGE];                // dst-bucketed (r<<16|src), packed
__device__ float g_e_part[12 * MROWS];              // token logit partials
__device__ float g_pool[BATCH * TOKD];              // pooled token rep
__device__ float g_ebuf[BATCH * NCTX];              // entity attention logits
__device__ float g_user[BATCH * KGD];               // user embedding
__device__ __align__(16) __half g_Xh[MROWS * TOKD]; // token_embedding in fp16
__device__ __align__(16) __half g_Wth[TOKD * TOKD]; // tok_W^T in fp16

// ---------------- small PTX helpers ----------------------------------------
__device__ __forceinline__ uint32_t smem_u32(const void* p) {
    uint32_t a;
    asm("{ .reg .u64 t; cvta.to.shared.u64 t, %1; cvt.u32.u64 %0, t; }"
        : "=r"(a) : "l"(p));
    return a;
}

__device__ __forceinline__ void cp16(uint32_t s, const void* g) {
    asm volatile("cp.async.cg.shared.global [%0], [%1], 16;"
                 :: "r"(s), "l"(g) : "memory");
}

__device__ __forceinline__ void mma16(float* c, const uint32_t* a,
                                      uint32_t b0, uint32_t b1) {
    asm volatile(
        "mma.sync.aligned.m16n8k16.row.col.f32.f16.f16.f32 "
        "{%0,%1,%2,%3}, {%4,%5,%6,%7}, {%8,%9}, {%0,%1,%2,%3};"
        : "+f"(c[0]), "+f"(c[1]), "+f"(c[2]), "+f"(c[3])
        : "r"(a[0]), "r"(a[1]), "r"(a[2]), "r"(a[3]), "r"(b0), "r"(b1));
}

__device__ __forceinline__ uint32_t pack_bf16(float a, float b) {
    __nv_bfloat162 h = __floats2bfloat162_rn(a, b);
    return *(uint32_t*)&h;
}

// ---------------- weight: wbf[r,n,d] = bf16( sum_b comp[r,b]*basis[b,n,d] )
__global__ void weight_kernel(const float* __restrict__ comp,
                              const float* __restrict__ basis) {
    __shared__ float c[N_RELS * N_BASES];
    int tid = threadIdx.x;
    if (tid < N_RELS * N_BASES) c[tid] = comp[tid];
    __syncthreads();

    int i = blockIdx.x * blockDim.x + tid;
    const int NM4 = (N_ENT * KGD) / 4;       // 960000
    if (i >= NM4) return;

    float4 bv[N_BASES];
    const float4* b4 = (const float4*)basis;
#pragma unroll
    for (int b = 0; b < N_BASES; b++) bv[b] = b4[(size_t)b * NM4 + i];

#pragma unroll
    for (int r = 0; r < N_RELS; r++) {
        float4 o = make_float4(0.f, 0.f, 0.f, 0.f);
#pragma unroll
        for (int b = 0; b < N_BASES; b++) {
            float cc = c[r * N_BASES + b];
            o.x += cc * bv[b].x; o.y += cc * bv[b].y;
            o.z += cc * bv[b].z; o.w += cc * bv[b].w;
        }
        uint2 p = make_uint2(pack_bf16(o.x, o.y), pack_bf16(o.z, o.w));
        *((uint2*)(g_wbf + ((size_t)r * NM4 + i) * 4)) = p;
    }
}

// ---------------- count: per-(rel,dst) counts + per-dst degree -------------
__global__ void count_kernel(const int* __restrict__ edge_index,
                             const int* __restrict__ edge_type) {
    int e = blockIdx.x * blockDim.x + threadIdx.x;
    if (e >= NEDGE) return;
    int r = edge_type[e];
    int d = edge_index[NEDGE + e];
    atomicAdd(&g_cnt[r * N_ENT + d], 1);
    atomicAdd(&g_deg[d], 1);
}

// ---------------- scan: exclusive scan of degree (single CTA, smem-staged) -
#define SCAN_PER 30   // 1024 * 30 = 30720 >= 30000
__global__ void scan_kernel() {
    extern __shared__ int sdeg[];        // 30000 ints (dynamic)
    __shared__ int part[1024];
    int t = threadIdx.x;

    for (int i = t; i < N_ENT / 4; i += 1024)
        ((int4*)sdeg)[i] = ((const int4*)g_deg)[i];
    __syncthreads();

    int base = t * SCAN_PER;
    int s = 0;
#pragma unroll
    for (int j = 0; j < SCAN_PER; j++) {
        int idx = base + j;
        if (idx < N_ENT) s += sdeg[idx];
    }
    part[t] = s;
    __syncthreads();
    for (int off = 1; off < 1024; off <<= 1) {
        int v = (t >= off) ? part[t - off] : 0;
        __syncthreads();
        part[t] += v;
        __syncthreads();
    }
    int run = part[t] - s;   // exclusive prefix
#pragma unroll
    for (int j = 0; j < SCAN_PER; j++) {
        int idx = base + j;
        if (idx < N_ENT) { int tmp = sdeg[idx]; sdeg[idx] = run; run += tmp; }
    }
    __syncthreads();

    for (int i = t; i < N_ENT / 4; i += 1024)
        ((int4*)g_off)[i] = ((const int4*)sdeg)[i];
    if (t == 1023) g_off[N_ENT] = part[1023];
}

// ---------------- place: bucket edges by dst (packed) ----------------------
__global__ void place_kernel(const int* __restrict__ edge_index,
                             const int* __restrict__ edge_type) {
    int e = blockIdx.x * blockDim.x + threadIdx.x;
    if (e >= NEDGE) return;
    int r = edge_type[e];
    int s = edge_index[e];
    int d = edge_index[NEDGE + e];
    int p = atomicAdd(&g_pos[d], 1);
    g_sorted[g_off[d] + p] = ((uint32_t)r << 16) | (uint32_t)s;
}

// ---------------- aggregate (2 warps per dst, 4-edge unroll) ----------------
__device__ __forceinline__ void agg_edge(uint32_t rec, int d, int lane,
                                         float& a0, float& a1, float& a2, float& a3) {
    int r = rec >> 16, s = rec & 0xffff;
    uint2 ww = *(const uint2*)(g_wbf + ((size_t)r * N_ENT + s) * KGD + lane * 4);
    int c = __ldg(&g_cnt[r * N_ENT + d]);
    float nn = 1.0f / (float)(c < 1 ? 1 : c);
    a0 += __uint_as_float(ww.x << 16)          * nn;
    a1 += __uint_as_float(ww.x & 0xffff0000u)  * nn;
    a2 += __uint_as_float(ww.y << 16)          * nn;
    a3 += __uint_as_float(ww.y & 0xffff0000u)  * nn;
}

__global__ void aggregate_kernel(const float* __restrict__ root,
                                 const float* __restrict__ bias) {
    __shared__ float4 part[4][32];
    int tpair = threadIdx.x >> 6;        // dst slot within block (0..3)
    int half = (threadIdx.x >> 5) & 1;   // edge-range half
    int lane = threadIdx.x & 31;
    int d = blockIdx.x * 4 + tpair;      // 7500 blocks * 4 = 30000 exactly
    if (d >= N_ENT) return;

    int beg = g_off[d], end = g_off[d + 1];
    int mid = (beg + end + 1) >> 1;
    int lo = half ? mid : beg;
    int hi = half ? end : mid;

    float a0 = 0.f, a1 = 0.f, a2 = 0.f, a3 = 0.f;
    int i = lo;
    for (; i + 4 <= hi; i += 4) {
        uint32_t rec0 = __ldg(&g_sorted[i]);
        uint32_t rec1 = __ldg(&g_sorted[i + 1]);
        uint32_t rec2 = __ldg(&g_sorted[i + 2]);
        uint32_t rec3 = __ldg(&g_sorted[i + 3]);
        int r0 = rec0 >> 16, s0 = rec0 & 0xffff;
        int r1 = rec1 >> 16, s1 = rec1 & 0xffff;
        int r2 = rec2 >> 16, s2 = rec2 & 0xffff;
        int r3 = rec3 >> 16, s3 = rec3 & 0xffff;
        uint2 w0 = *(const uint2*)(g_wbf + ((size_t)r0 * N_ENT + s0) * KGD + lane * 4);
        uint2 w1 = *(const uint2*)(g_wbf + ((size_t)r1 * N_ENT + s1) * KGD + lane * 4);
        uint2 w2 = *(const uint2*)(g_wbf + ((size_t)r2 * N_ENT + s2) * KGD + lane * 4);
        uint2 w3 = *(const uint2*)(g_wbf + ((size_t)r3 * N_ENT + s3) * KGD + lane * 4);
        int c0 = __ldg(&g_cnt[r0 * N_ENT + d]);
        int c1 = __ldg(&g_cnt[r1 * N_ENT + d]);
        int c2 = __ldg(&g_cnt[r2 * N_ENT + d]);
        int c3 = __ldg(&g_cnt[r3 * N_ENT + d]);
        float n0 = 1.0f / (float)(c0 < 1 ? 1 : c0);
        float n1 = 1.0f / (float)(c1 < 1 ? 1 : c1);
        float n2 = 1.0f / (float)(c2 < 1 ? 1 : c2);
        float n3 = 1.0f / (float)(c3 < 1 ? 1 : c3);
        a0 += __uint_as_float(w0.x << 16) * n0 + __uint_as_float(w1.x << 16) * n1
            + __uint_as_float(w2.x << 16) * n2 + __uint_as_float(w3.x << 16) * n3;
        a1 += __uint_as_float(w0.x & 0xffff0000u) * n0 + __uint_as_float(w1.x & 0xffff0000u) * n1
            + __uint_as_float(w2.x & 0xffff0000u) * n2 + __uint_as_float(w3.x & 0xffff0000u) * n3;
        a2 += __uint_as_float(w0.y << 16) * n0 + __uint_as_float(w1.y << 16) * n1
            + __uint_as_float(w2.y << 16) * n2 + __uint_as_float(w3.y << 16) * n3;
        a3 += __uint_as_float(w0.y & 0xffff0000u) * n0 + __uint_as_float(w1.y & 0xffff0000u) * n1
            + __uint_as_float(w2.y & 0xffff0000u) * n2 + __uint_as_float(w3.y & 0xffff0000u) * n3;
    }
    for (; i < hi; i++)
        agg_edge(__ldg(&g_sorted[i]), d, lane, a0, a1, a2, a3);

    if (half == 1) part[tpair][lane] = make_float4(a0, a1, a2, a3);
    __syncthreads();
    if (half == 0) {
        float4 p = part[tpair][lane];
        int o = d * KGD + lane * 4;
        float4 r4 = *(const float4*)(root + o);
        float4 b4 = *(const float4*)(bias + lane * 4);
        float4 outv = make_float4(a0 + p.x + r4.x + b4.x, a1 + p.y + r4.y + b4.y,
                                  a2 + p.z + r4.z + b4.z, a3 + p.w + r4.w + b4.w);
        *(float4*)(g_kg + o) = outv;
    }
}

// ---------------- entity logits: one warp per (b, l) -----------------------
__global__ void __launch_bounds__(1024, 1)
ent_logits_kernel(const int* __restrict__ ctx_ent,
                  const float* __restrict__ entW,
                  const float* __restrict__ entb,
                  const float* __restrict__ entv) {
    int l = blockIdx.x;              // 0..NCTX-1
    int b = threadIdx.x >> 5;        // 0..31 (batch)
    int lane = threadIdx.x & 31;

    int id = __ldg(&ctx_ent[b * NCTX + l]);
    float4 rep = *(const float4*)(g_kg + (size_t)id * KGD + lane * 4);
    float4 h = *(const float4*)(entb + lane * 4);
    const float4* Wp = (const float4*)entW;

#pragma unroll 8
    for (int dq = 0; dq < 32; dq++) {
        float rx = __shfl_sync(0xffffffffu, rep.x, dq);
        float ry = __shfl_sync(0xffffffffu, rep.y, dq);
        float rz = __shfl_sync(0xffffffffu, rep.z, dq);
        float rw = __shfl_sync(0xffffffffu, rep.w, dq);
        float4 w0 = Wp[(dq * 4 + 0) * 32 + lane];
        float4 w1 = Wp[(dq * 4 + 1) * 32 + lane];
        float4 w2 = Wp[(dq * 4 + 2) * 32 + lane];
        float4 w3 = Wp[(dq * 4 + 3) * 32 + lane];
        h.x += rx * w0.x + ry * w1.x + rz * w2.x + rw * w3.x;
        h.y += rx * w0.y + ry * w1.y + rz * w2.y + rw * w3.y;
        h.z += rx * w0.z + ry * w1.z + rz * w2.z + rw * w3.z;
        h.w += rx * w0.w + ry * w1.w + rz * w2.w + rw * w3.w;
    }
    float4 v = *(const float4*)(entv + lane * 4);
    float e = tanhf(h.x) * v.x + tanhf(h.y) * v.y
            + tanhf(h.z) * v.z + tanhf(h.w) * v.w;
#pragma unroll
    for (int off = 16; off > 0; off >>= 1)
        e += __shfl_down_sync(0xffffffffu, e, off);
    if (lane == 0) g_ebuf[b * NCTX + l] = e;
}

// ---------------- prep = X->fp16 convert + W transpose (merged) ------------
#define XCVT_BLOCKS ((MROWS * TOKD / 4 + 255) / 256)   // 6144
__global__ void prep_kernel(const float* __restrict__ X,
                            const float* __restrict__ W) {
    if (blockIdx.x < XCVT_BLOCKS) {
        int i = blockIdx.x * 256 + threadIdx.x;   // float4 index
        const int N4 = MROWS * TOKD / 4;
        if (i >= N4) return;
        float4 v = ((const float4*)X)[i];
        __half2 h0 = __floats2half2_rn(v.x, v.y);
        __half2 h1 = __floats2half2_rn(v.z, v.w);
        uint2 p = make_uint2(*(uint32_t*)&h0, *(uint32_t*)&h1);
        ((uint2*)g_Xh)[i] = p;
    } else {
        __shared__ float t[32][33];
        int idx = blockIdx.x - XCVT_BLOCKS;       // 0..575
        int bx = (idx % (TOKD / 32)) * 32;
        int by = (idx / (TOKD / 32)) * 32;
        int tx = threadIdx.x & 31, ty = threadIdx.x >> 5;  // 32 x 8
#pragma unroll
        for (int i = 0; i < 32; i += 8)
            t[ty + i][tx] = W[(size_t)(by + ty + i) * TOKD + bx + tx];
        __syncthreads();
#pragma unroll
        for (int i = 0; i < 32; i += 8)
            g_Wth[(size_t)(bx + ty + i) * TOKD + by + tx] = __float2half(t[tx][ty + i]);
    }
}

// ---------------- token attention logits via mma.sync fp16 -----------------
#define KCH 32
#define NCHUNK (TOKD / KCH)   // 24
#define LDH 40                // smem row stride in halves (32 + 8 pad = 80B)

__device__ __forceinline__ void issue_chunk(int row0, int col0, int c,
                                            __half* Asm, __half* Bsm, int tid) {
    int k0 = c * KCH;
#pragma unroll
    for (int i = 0; i < 2; i++) {
        int f = tid + i * 256;              // 0..511
        int rr = f >> 2;                    // 0..127
        int seg = (f & 3) * 8;              // 0,8,16,24 halves
        cp16(smem_u32(Asm + rr * LDH + seg),
             g_Xh + (size_t)(row0 + rr) * TOKD + k0 + seg);
        cp16(smem_u32(Bsm + rr * LDH + seg),
             g_Wth + (size_t)(col0 + rr) * TOKD + k0 + seg);
    }
    asm volatile("cp.async.commit_group;" ::: "memory");
}

__global__ void __launch_bounds__(256, 2)
tok_gemm_fp16(const float* __restrict__ tokb,
              const float* __restrict__ tokv) {
    __shared__ __half As[2][128 * LDH];
    __shared__ __half Bs[2][128 * LDH];

    int tid = threadIdx.x;
    int wid = tid >> 5, lane = tid & 31;
    int gid = lane >> 2, tig = lane & 3;
    int warpM = wid >> 1, warpN = wid & 1;
    int row0 = blockIdx.x * 128, col0 = blockIdx.y * 128;

    float acc[2][8][4];
#pragma unroll
    for (int mi = 0; mi < 2; mi++)
#pragma unroll
        for (int nj = 0; nj < 8; nj++)
#pragma unroll
            for (int q = 0; q < 4; q++) acc[mi][nj][q] = 0.f;

    issue_chunk(row0, col0, 0, As[0], Bs[0], tid);

    for (int c = 0; c < NCHUNK; c++) {
        if (c + 1 < NCHUNK) {
            issue_chunk(row0, col0, c + 1, As[(c + 1) & 1], Bs[(c + 1) & 1], tid);
            asm volatile("cp.async.wait_group 1;" ::: "memory");
        } else {
            asm volatile("cp.async.wait_group 0;" ::: "memory");
        }
        __syncthreads();

        const __half* Ab = As[c & 1];
        const __half* Bb = Bs[c & 1];
#pragma unroll
        for (int ks = 0; ks < 2; ks++) {
            int kh = ks * 16 + 2 * tig;
            uint32_t a[2][4];
#pragma unroll
            for (int mi = 0; mi < 2; mi++) {
                int rb = warpM * 32 + mi * 16 + gid;
                a[mi][0] = *(const uint32_t*)(Ab + rb * LDH + kh);
                a[mi][1] = *(const uint32_t*)(Ab + (rb + 8) * LDH + kh);
                a[mi][2] = *(const uint32_t*)(Ab + rb * LDH + kh + 8);
                a[mi][3] = *(const uint32_t*)(Ab + (rb + 8) * LDH + kh + 8);
            }
#pragma unroll
            for (int nj = 0; nj < 8; nj++) {
                int nb = warpN * 64 + nj * 8 + gid;
                uint32_t b0 = *(const uint32_t*)(Bb + nb * LDH + kh);
                uint32_t b1 = *(const uint32_t*)(Bb + nb * LDH + kh + 8);
                mma16(acc[0][nj], a[0], b0, b1);
                mma16(acc[1][nj], a[1], b0, b1);
            }
        }
        __syncthreads();
    }

    // epilogue: per-(col-tile, warpN) partial row sums, no atomics
    float rsum[2][2] = {{0.f, 0.f}, {0.f, 0.f}};
#pragma unroll
    for (int mi = 0; mi < 2; mi++) {
#pragma unroll
        for (int nj = 0; nj < 8; nj++) {
            int n0 = col0 + warpN * 64 + nj * 8 + 2 * tig;
            float bb0 = __ldg(&tokb[n0]), bb1 = __ldg(&tokb[n0 + 1]);
            float vv0 = __ldg(&tokv[n0]), vv1 = __ldg(&tokv[n0 + 1]);
            rsum[mi][0] += tanhf(acc[mi][nj][0] + bb0) * vv0
                         + tanhf(acc[mi][nj][1] + bb1) * vv1;
            rsum[mi][1] += tanhf(acc[mi][nj][2] + bb0) * vv0
                         + tanhf(acc[mi][nj][3] + bb1) * vv1;
        }
    }
    int slot = blockIdx.y * 2 + warpN;   // 0..11
#pragma unroll
    for (int mi = 0; mi < 2; mi++)
#pragma unroll
        for (int h = 0; h < 2; h++) {
            float s = rsum[mi][h];
            s += __shfl_xor_sync(0xffffffffu, s, 1);
            s += __shfl_xor_sync(0xffffffffu, s, 2);
            if (tig == 0)
                g_e_part[slot * MROWS + row0 + warpM * 32 + mi * 16 + h * 8 + gid] = s;
        }
}

// ---------------- tok_pool: fused masked softmax + pooling (fp16 X) --------
__global__ void tok_pool_kernel(const int* __restrict__ ctx_tok) {
    int b = blockIdx.x;
    int dc = blockIdx.y;     // 0..2
    int tid = threadIdx.x;   // 0..255
    __shared__ float red[SEQL];
    __shared__ float a[SEQL];
    __shared__ float2 part[128];

    int row = b * SEQL + tid;
    float ev = 0.f;
#pragma unroll
    for (int j = 0; j < 12; j++) ev += g_e_part[j * MROWS + row];
    float val = (ctx_tok[row] != 0) ? ev : -1e9f;

    red[tid] = val;
    __syncthreads();
    for (int s = 128; s > 0; s >>= 1) {
        if (tid < s) red[tid] = fmaxf(red[tid], red[tid + s]);
        __syncthreads();
    }
    float mx = red[0];
    __syncthreads();
    float ex = expf(val - mx);
    red[tid] = ex;
    __syncthreads();
    for (int s = 128; s > 0; s >>= 1) {
        if (tid < s) red[tid] += red[tid + s];
        __syncthreads();
    }
    a[tid] = ex / red[0];
    __syncthreads();

    int h2 = tid & 127;
    int sh = tid >> 7;       // sequence half
    const __half2* xp = (const __half2*)(g_Xh + (size_t)b * SEQL * TOKD)
                        + dc * 128 + h2 + (size_t)(sh * 128) * (TOKD / 2);
    const float* ap = a + sh * 128;
    const int strid = TOKD / 2;
    float s0 = 0.f, s1 = 0.f, s2 = 0.f, s3 = 0.f;
#pragma unroll 4
    for (int l = 0; l < 128; l += 2) {
        float2 f0 = __half22float2(xp[(size_t)l * strid]);
        float2 f1 = __half22float2(xp[(size_t)(l + 1) * strid]);
        s0 += ap[l] * f0.x;  s1 += ap[l] * f0.y;
        s2 += ap[l + 1] * f1.x;  s3 += ap[l + 1] * f1.y;
    }
    float2 mine = make_float2(s0 + s2, s1 + s3);
    if (sh == 1) part[h2] = mine;
    __syncthreads();
    if (sh == 0) {
        float2 other = part[h2];
        float2 outv = make_float2(mine.x + other.x, mine.y + other.y);
        *(float2*)(g_pool + b * TOKD + dc * 256 + h2 * 2) = outv;
    }
}

// ---------------- gate: ent softmax+combine, linear, gate, user ------------
__global__ void gate_kernel(const int* __restrict__ ctx_ent,
                            const float* __restrict__ linW,
                            const float* __restrict__ linb,
                            const float* __restrict__ gateW,
                            const float* __restrict__ gateb) {
    int b = blockIdx.x;
    int tid = threadIdx.x;   // 0..127
    int wid = tid >> 5, lane = tid & 31;
    __shared__ float pool[TOKD];
    __shared__ float cat[2 * KGD];   // [tokr | entr]
    __shared__ int ids[NCTX];
    __shared__ float aw[NCTX];

    for (int i = tid; i < TOKD; i += 128) pool[i] = g_pool[b * TOKD + i];
    if (tid < NCTX) ids[tid] = __ldg(&ctx_ent[b * NCTX + tid]);
    __syncthreads();

    if (tid == 0) {
        float mx = -1e30f;
        float eb[NCTX];
        for (int l = 0; l < NCTX; l++) {
            float v = (ids[l] != 0) ? g_ebuf[b * NCTX + l] : -1e9f;
            eb[l] = v;
            mx = fmaxf(mx, v);
        }
        float sum = 0.f;
        for (int l = 0; l < NCTX; l++) { aw[l] = expf(eb[l] - mx); sum += aw[l]; }
        float inv = 1.0f / sum;
        for (int l = 0; l < NCTX; l++) aw[l] *= inv;
    }
    __syncthreads();

    {
        float er = 0.f;
        for (int l = 0; l < NCTX; l++)
            er += aw[l] * g_kg[(size_t)ids[l] * KGD + tid];
        cat[KGD + tid] = er;
    }
    __syncthreads();

    for (int o = wid * 32; o < wid * 32 + 32; o++) {
        const float4* wp = (const float4*)(linW + (size_t)o * TOKD);
        float s = 0.f;
#pragma unroll
        for (int d4 = lane; d4 < TOKD / 4; d4 += 32) {
            float4 w4 = wp[d4];
            float4 p4 = *(const float4*)&pool[d4 * 4];
            s += w4.x * p4.x + w4.y * p4.y + w4.z * p4.z + w4.w * p4.w;
        }
#pragma unroll
        for (int off = 16; off > 0; off >>= 1) s += __shfl_down_sync(0xffffffffu, s, off);
        if (lane == 0) cat[o] = s + linb[o];
    }
    __syncthreads();

    for (int o = wid * 32; o < wid * 32 + 32; o++) {
        const float4* gw = (const float4*)(gateW + (size_t)o * (2 * KGD));
        float s = 0.f;
#pragma unroll
        for (int k4 = lane; k4 < (2 * KGD) / 4; k4 += 32) {
            float4 w4 = gw[k4];
            float4 c4 = *(const float4*)&cat[k4 * 4];
            s += w4.x * c4.x + w4.y * c4.y + w4.z * c4.z + w4.w * c4.w;
        }
#pragma unroll
        for (int off = 16; off > 0; off >>= 1) s += __shfl_down_sync(0xffffffffu, s, off);
        if (lane == 0) {
            float g = 1.0f / (1.0f + expf(-(s + gateb[o])));
            g_user[b * KGD + o] = g * cat[o] + (1.0f - g) * cat[KGD + o];
        }
    }
}

// ---------------- scores = user @ kg^T --------------------------------------
__global__ void scores_kernel(float* __restrict__ out) {
    __shared__ float U[BATCH * KGD];
    int tid = threadIdx.x;
    for (int i = tid; i < BATCH * KGD; i += 256) U[i] = g_user[i];
    __syncthreads();

    int n = blockIdx.x * 256 + tid;
    if (n >= N_ENT) return;

    float acc[BATCH];
#pragma unroll
    for (int b = 0; b < BATCH; b++) acc[b] = 0.f;

    const float4* kgp = (const float4*)(g_kg + (size_t)n * KGD);
#pragma unroll 4
    for (int d4 = 0; d4 < KGD / 4; d4++) {
        float4 kv = kgp[d4];
#pragma unroll
        for (int b = 0; b < BATCH; b++) {
            float4 uv = *(const float4*)&U[b * KGD + d4 * 4];
            acc[b] += kv.x * uv.x + kv.y * uv.y + kv.z * uv.z + kv.w * uv.w;
        }
    }
#pragma unroll
    for (int b = 0; b < BATCH; b++) out[(size_t)b * N_ENT + n] = acc[b];
}

// ---------------- launch ----------------------------------------------------
extern "C" void kernel_launch(void* const* d_in, const int* in_sizes, int n_in,
                              void* d_out, int out_size) {
    const int*   ctx_ent  = (const int*)d_in[0];
    const int*   ctx_tok  = (const int*)d_in[1];
    const int*   edge_idx = (const int*)d_in[2];
    const int*   edge_typ = (const int*)d_in[3];
    const float* tok_emb  = (const float*)d_in[4];
    const float* comp     = (const float*)d_in[5];
    const float* basis    = (const float*)d_in[6];
    const float* root     = (const float*)d_in[7];
    const float* rg_bias  = (const float*)d_in[8];
    const float* entW     = (const float*)d_in[9];
    const float* entb     = (const float*)d_in[10];
    const float* entv     = (const float*)d_in[11];
    const float* tokW     = (const float*)d_in[12];
    const float* tokb     = (const float*)d_in[13];
    const float* tokv     = (const float*)d_in[14];
    const float* linW     = (const float*)d_in[15];
    const float* linb     = (const float*)d_in[16];
    const float* gateW    = (const float*)d_in[17];
    const float* gateb    = (const float*)d_in[18];
    float* out = (float*)d_out;

    cudaFuncSetAttribute(scan_kernel,
                         cudaFuncAttributeMaxDynamicSharedMemorySize,
                         N_ENT * (int)sizeof(int));

    void *p_cnt = nullptr, *p_deg = nullptr, *p_pos = nullptr;
    cudaGetSymbolAddress(&p_cnt, g_cnt);
    cudaGetSymbolAddress(&p_deg, g_deg);
    cudaGetSymbolAddress(&p_pos, g_pos);

    cudaStream_t s1, s2, s3;
    cudaEvent_t e0, ew, ep, ea, ee;
    cudaStreamCreateWithFlags(&s1, cudaStreamNonBlocking);
    cudaStreamCreateWithFlags(&s2, cudaStreamNonBlocking);
    cudaStreamCreateWithFlags(&s3, cudaStreamNonBlocking);
    cudaEventCreateWithFlags(&e0, cudaEventDisableTiming);
    cudaEventCreateWithFlags(&ew, cudaEventDisableTiming);
    cudaEventCreateWithFlags(&ep, cudaEventDisableTiming);
    cudaEventCreateWithFlags(&ea, cudaEventDisableTiming);
    cudaEventCreateWithFlags(&ee, cudaEventDisableTiming);

    // fork
    cudaEventRecord(e0, 0);
    cudaStreamWaitEvent(s1, e0, 0);
    cudaStreamWaitEvent(s2, e0, 0);
    cudaStreamWaitEvent(s3, e0, 0);

    // s1: RGCN weight table — kernel submission #1
    weight_kernel<<<(960000 + 255) / 256, 256, 0, s1>>>(comp, basis);    // #1
    cudaEventRecord(ew, s1);

    // main: graph bookkeeping (memsets are not kernels)
    cudaMemsetAsync(p_cnt, 0, N_RELS * N_ENT * sizeof(int), 0);
    cudaMemsetAsync(p_deg, 0, N_ENT * sizeof(int), 0);
    cudaMemsetAsync(p_pos, 0, N_ENT * sizeof(int), 0);
    count_kernel<<<(NEDGE + 255) / 256, 256>>>(edge_idx, edge_typ);      // #2
    scan_kernel<<<1, 1024, N_ENT * sizeof(int)>>>();                     // #3
    place_kernel<<<(NEDGE + 255) / 256, 256>>>(edge_idx, edge_typ);      // #4 (profiled)

    // s2: token path (executes from t=0; submission order is irrelevant
    // to execution order inside the captured graph)
    prep_kernel<<<XCVT_BLOCKS + (TOKD / 32) * (TOKD / 32), 256, 0, s2>>>(tok_emb, tokW); // #5
    tok_gemm_fp16<<<dim3(64, 6), 256, 0, s2>>>(tokb, tokv);              // #6
    tok_pool_kernel<<<dim3(BATCH, 3), 256, 0, s2>>>(ctx_tok);            // #7
    cudaEventRecord(ep, s2);

    // join weight -> aggregate (2 warps/dst)
    cudaStreamWaitEvent(0, ew, 0);
    aggregate_kernel<<<N_ENT / 4, 256>>>(root, rg_bias);                 // #8
    cudaEventRecord(ea, 0);

    // s3: entity logits after aggregate
    cudaStreamWaitEvent(s3, ea, 0);
    ent_logits_kernel<<<NCTX, 1024, 0, s3>>>(ctx_ent, entW, entb, entv); // #9
    cudaEventRecord(ee, s3);

    // join all -> gate, scores
    cudaStreamWaitEvent(0, ep, 0);
    cudaStreamWaitEvent(0, ee, 0);
    gate_kernel<<<BATCH, 128>>>(ctx_ent, linW, linb, gateW, gateb);      // #10
    scores_kernel<<<(N_ENT + 255) / 256, 256>>>(out);                    // #11

    cudaEventDestroy(e0);
    cudaEventDestroy(ew);
    cudaEventDestroy(ep);
    cudaEventDestroy(ea);
    cudaEventDestroy(ee);
    cudaStreamDestroy(s1);
    cudaStreamDestroy(s2);
    cudaStreamDestroy(s3);
}

// round 15
// speedup vs baseline: 1.1415x; 1.1415x over previous
#include <cuda_runtime.h>
#include <cuda_bf16.h>
#include <cuda_fp16.h>
#include <cstdint>

#define N_ENT   30000
#define N_RELS  12
#define N_BASES 8
#define KGD     128
#define TOKD    768
#define BATCH   32
#define NCTX    50
#define SEQL    256
#define NEDGE   400000
#define MROWS   (BATCH * SEQL)   // 8192

// ---------------- scratch (__device__ globals; no allocations allowed) ----
__device__ __align__(256) __nv_bfloat16 g_wbf[N_RELS * N_ENT * KGD]; // 92 MB bf16 weights
__device__ float g_kg[N_ENT * KGD];                 // kg_embedding
__device__ int   g_cnt[N_RELS * N_ENT];             // per (rel,dst) edge counts
__device__ __align__(16) int g_deg[N_ENT];          // per-dst degree
__device__ __align__(16) int g_off[N_ENT + 4];      // exclusive scan of degree
__device__ int   g_pos[N_ENT];                      // running placement counters
__device__ uint32_t g_sorted[NEDGE];                // dst-bucketed (r<<16|src), packed
__device__ float g_e_part[12 * MROWS];              // token logit partials
__device__ float g_pool[BATCH * TOKD];              // pooled token rep
__device__ float g_ebuf[BATCH * NCTX];              // entity attention logits
__device__ float g_user[BATCH * KGD];               // user embedding
__device__ __align__(16) __half g_Xh[MROWS * TOKD]; // token_embedding in fp16
__device__ __align__(16) __half g_Wth[TOKD * TOKD]; // tok_W^T in fp16

// ---------------- small PTX helpers ----------------------------------------
__device__ __forceinline__ uint32_t smem_u32(const void* p) {
    uint32_t a;
    asm("{ .reg .u64 t; cvta.to.shared.u64 t, %1; cvt.u32.u64 %0, t; }"
        : "=r"(a) : "l"(p));
    return a;
}

__device__ __forceinline__ void cp16(uint32_t s, const void* g) {
    asm volatile("cp.async.cg.shared.global [%0], [%1], 16;"
                 :: "r"(s), "l"(g) : "memory");
}

__device__ __forceinline__ void mma16(float* c, const uint32_t* a,
                                      uint32_t b0, uint32_t b1) {
    asm volatile(
        "mma.sync.aligned.m16n8k16.row.col.f32.f16.f16.f32 "
        "{%0,%1,%2,%3}, {%4,%5,%6,%7}, {%8,%9}, {%0,%1,%2,%3};"
        : "+f"(c[0]), "+f"(c[1]), "+f"(c[2]), "+f"(c[3])
        : "r"(a[0]), "r"(a[1]), "r"(a[2]), "r"(a[3]), "r"(b0), "r"(b1));
}

__device__ __forceinline__ uint32_t pack_bf16(float a, float b) {
    __nv_bfloat162 h = __floats2bfloat162_rn(a, b);
    return *(uint32_t*)&h;
}

// ---------------- weight: wbf[r,n,d] = bf16( sum_b comp[r,b]*basis[b,n,d] )
__global__ void weight_kernel(const float* __restrict__ comp,
                              const float* __restrict__ basis) {
    __shared__ float c[N_RELS * N_BASES];
    int tid = threadIdx.x;
    if (tid < N_RELS * N_BASES) c[tid] = comp[tid];
    __syncthreads();

    int i = blockIdx.x * blockDim.x + tid;
    const int NM4 = (N_ENT * KGD) / 4;       // 960000
    if (i >= NM4) return;

    float4 bv[N_BASES];
    const float4* b4 = (const float4*)basis;
#pragma unroll
    for (int b = 0; b < N_BASES; b++) bv[b] = b4[(size_t)b * NM4 + i];

#pragma unroll
    for (int r = 0; r < N_RELS; r++) {
        float4 o = make_float4(0.f, 0.f, 0.f, 0.f);
#pragma unroll
        for (int b = 0; b < N_BASES; b++) {
            float cc = c[r * N_BASES + b];
            o.x += cc * bv[b].x; o.y += cc * bv[b].y;
            o.z += cc * bv[b].z; o.w += cc * bv[b].w;
        }
        uint2 p = make_uint2(pack_bf16(o.x, o.y), pack_bf16(o.z, o.w));
        *((uint2*)(g_wbf + ((size_t)r * NM4 + i) * 4)) = p;
    }
}

// ---------------- count: per-(rel,dst) counts + per-dst degree -------------
__global__ void count_kernel(const int* __restrict__ edge_index,
                             const int* __restrict__ edge_type) {
    int e = blockIdx.x * blockDim.x + threadIdx.x;
    if (e >= NEDGE) return;
    int r = edge_type[e];
    int d = edge_index[NEDGE + e];
    atomicAdd(&g_cnt[r * N_ENT + d], 1);
    atomicAdd(&g_deg[d], 1);
}

// ---------------- scan: exclusive scan of degree (single CTA, smem-staged) -
#define SCAN_PER 30   // 1024 * 30 = 30720 >= 30000
__global__ void scan_kernel() {
    extern __shared__ int sdeg[];        // 30000 ints (dynamic)
    __shared__ int part[1024];
    int t = threadIdx.x;

    for (int i = t; i < N_ENT / 4; i += 1024)
        ((int4*)sdeg)[i] = ((const int4*)g_deg)[i];
    __syncthreads();

    int base = t * SCAN_PER;
    int s = 0;
#pragma unroll
    for (int j = 0; j < SCAN_PER; j++) {
        int idx = base + j;
        if (idx < N_ENT) s += sdeg[idx];
    }
    part[t] = s;
    __syncthreads();
    for (int off = 1; off < 1024; off <<= 1) {
        int v = (t >= off) ? part[t - off] : 0;
        __syncthreads();
        part[t] += v;
        __syncthreads();
    }
    int run = part[t] - s;   // exclusive prefix
#pragma unroll
    for (int j = 0; j < SCAN_PER; j++) {
        int idx = base + j;
        if (idx < N_ENT) { int tmp = sdeg[idx]; sdeg[idx] = run; run += tmp; }
    }
    __syncthreads();

    for (int i = t; i < N_ENT / 4; i += 1024)
        ((int4*)g_off)[i] = ((const int4*)sdeg)[i];
    if (t == 1023) g_off[N_ENT] = part[1023];
}

// ---------------- place: bucket edges by dst (packed) ----------------------
__global__ void place_kernel(const int* __restrict__ edge_index,
                             const int* __restrict__ edge_type) {
    int e = blockIdx.x * blockDim.x + threadIdx.x;
    if (e >= NEDGE) return;
    int r = edge_type[e];
    int s = edge_index[e];
    int d = edge_index[NEDGE + e];
    int p = atomicAdd(&g_pos[d], 1);
    g_sorted[g_off[d] + p] = ((uint32_t)r << 16) | (uint32_t)s;
}

// ---------------- aggregate (1 warp per dst, 4-edge unroll) — R13 version --
__device__ __forceinline__ void agg_edge(uint32_t rec, int d, int lane,
                                         float& a0, float& a1, float& a2, float& a3) {
    int r = rec >> 16, s = rec & 0xffff;
    uint2 ww = *(const uint2*)(g_wbf + ((size_t)r * N_ENT + s) * KGD + lane * 4);
    int c = __ldg(&g_cnt[r * N_ENT + d]);
    float nn = 1.0f / (float)(c < 1 ? 1 : c);
    a0 += __uint_as_float(ww.x << 16)          * nn;
    a1 += __uint_as_float(ww.x & 0xffff0000u)  * nn;
    a2 += __uint_as_float(ww.y << 16)          * nn;
    a3 += __uint_as_float(ww.y & 0xffff0000u)  * nn;
}

__global__ void aggregate_kernel(const float* __restrict__ root,
                                 const float* __restrict__ bias) {
    int w = (blockIdx.x * blockDim.x + threadIdx.x) >> 5;
    int lane = threadIdx.x & 31;
    if (w >= N_ENT) return;
    int d = w;
    int beg = g_off[d], end = g_off[d + 1];

    float a0 = 0.f, a1 = 0.f, a2 = 0.f, a3 = 0.f;
    int i = beg;
    for (; i + 4 <= end; i += 4) {
        uint32_t rec0 = __ldg(&g_sorted[i]);
        uint32_t rec1 = __ldg(&g_sorted[i + 1]);
        uint32_t rec2 = __ldg(&g_sorted[i + 2]);
        uint32_t rec3 = __ldg(&g_sorted[i + 3]);
        int r0 = rec0 >> 16, s0 = rec0 & 0xffff;
        int r1 = rec1 >> 16, s1 = rec1 & 0xffff;
        int r2 = rec2 >> 16, s2 = rec2 & 0xffff;
        int r3 = rec3 >> 16, s3 = rec3 & 0xffff;
        uint2 w0 = *(const uint2*)(g_wbf + ((size_t)r0 * N_ENT + s0) * KGD + lane * 4);
        uint2 w1 = *(const uint2*)(g_wbf + ((size_t)r1 * N_ENT + s1) * KGD + lane * 4);
        uint2 w2 = *(const uint2*)(g_wbf + ((size_t)r2 * N_ENT + s2) * KGD + lane * 4);
        uint2 w3 = *(const uint2*)(g_wbf + ((size_t)r3 * N_ENT + s3) * KGD + lane * 4);
        int c0 = __ldg(&g_cnt[r0 * N_ENT + d]);
        int c1 = __ldg(&g_cnt[r1 * N_ENT + d]);
        int c2 = __ldg(&g_cnt[r2 * N_ENT + d]);
        int c3 = __ldg(&g_cnt[r3 * N_ENT + d]);
        float n0 = 1.0f / (float)(c0 < 1 ? 1 : c0);
        float n1 = 1.0f / (float)(c1 < 1 ? 1 : c1);
        float n2 = 1.0f / (float)(c2 < 1 ? 1 : c2);
        float n3 = 1.0f / (float)(c3 < 1 ? 1 : c3);
        a0 += __uint_as_float(w0.x << 16) * n0 + __uint_as_float(w1.x << 16) * n1
            + __uint_as_float(w2.x << 16) * n2 + __uint_as_float(w3.x << 16) * n3;
        a1 += __uint_as_float(w0.x & 0xffff0000u) * n0 + __uint_as_float(w1.x & 0xffff0000u) * n1
            + __uint_as_float(w2.x & 0xffff0000u) * n2 + __uint_as_float(w3.x & 0xffff0000u) * n3;
        a2 += __uint_as_float(w0.y << 16) * n0 + __uint_as_float(w1.y << 16) * n1
            + __uint_as_float(w2.y << 16) * n2 + __uint_as_float(w3.y << 16) * n3;
        a3 += __uint_as_float(w0.y & 0xffff0000u) * n0 + __uint_as_float(w1.y & 0xffff0000u) * n1
            + __uint_as_float(w2.y & 0xffff0000u) * n2 + __uint_as_float(w3.y & 0xffff0000u) * n3;
    }
    for (; i < end; i++)
        agg_edge(__ldg(&g_sorted[i]), d, lane, a0, a1, a2, a3);

    int o = d * KGD + lane * 4;
    float4 r4 = *(const float4*)(root + o);
    float4 b4 = *(const float4*)(bias + lane * 4);
    float4 outv = make_float4(a0 + r4.x + b4.x, a1 + r4.y + b4.y,
                              a2 + r4.z + b4.z, a3 + r4.w + b4.w);
    *(float4*)(g_kg + o) = outv;
}

// ---------------- entity logits: one warp per (b, l) -----------------------
__global__ void __launch_bounds__(1024, 1)
ent_logits_kernel(const int* __restrict__ ctx_ent,
                  const float* __restrict__ entW,
                  const float* __restrict__ entb,
                  const float* __restrict__ entv) {
    int l = blockIdx.x;              // 0..NCTX-1
    int b = threadIdx.x >> 5;        // 0..31 (batch)
    int lane = threadIdx.x & 31;

    int id = __ldg(&ctx_ent[b * NCTX + l]);
    float4 rep = *(const float4*)(g_kg + (size_t)id * KGD + lane * 4);
    float4 h = *(const float4*)(entb + lane * 4);
    const float4* Wp = (const float4*)entW;

#pragma unroll 8
    for (int dq = 0; dq < 32; dq++) {
        float rx = __shfl_sync(0xffffffffu, rep.x, dq);
        float ry = __shfl_sync(0xffffffffu, rep.y, dq);
        float rz = __shfl_sync(0xffffffffu, rep.z, dq);
        float rw = __shfl_sync(0xffffffffu, rep.w, dq);
        float4 w0 = Wp[(dq * 4 + 0) * 32 + lane];
        float4 w1 = Wp[(dq * 4 + 1) * 32 + lane];
        float4 w2 = Wp[(dq * 4 + 2) * 32 + lane];
        float4 w3 = Wp[(dq * 4 + 3) * 32 + lane];
        h.x += rx * w0.x + ry * w1.x + rz * w2.x + rw * w3.x;
        h.y += rx * w0.y + ry * w1.y + rz * w2.y + rw * w3.y;
        h.z += rx * w0.z + ry * w1.z + rz * w2.z + rw * w3.z;
        h.w += rx * w0.w + ry * w1.w + rz * w2.w + rw * w3.w;
    }
    float4 v = *(const float4*)(entv + lane * 4);
    float e = tanhf(h.x) * v.x + tanhf(h.y) * v.y
            + tanhf(h.z) * v.z + tanhf(h.w) * v.w;
#pragma unroll
    for (int off = 16; off > 0; off >>= 1)
        e += __shfl_down_sync(0xffffffffu, e, off);
    if (lane == 0) g_ebuf[b * NCTX + l] = e;
}

// ---------------- prep = X->fp16 convert + W transpose (merged) ------------
#define XCVT_BLOCKS ((MROWS * TOKD / 4 + 255) / 256)   // 6144
__global__ void prep_kernel(const float* __restrict__ X,
                            const float* __restrict__ W) {
    if (blockIdx.x < XCVT_BLOCKS) {
        int i = blockIdx.x * 256 + threadIdx.x;   // float4 index
        const int N4 = MROWS * TOKD / 4;
        if (i >= N4) return;
        float4 v = ((const float4*)X)[i];
        __half2 h0 = __floats2half2_rn(v.x, v.y);
        __half2 h1 = __floats2half2_rn(v.z, v.w);
        uint2 p = make_uint2(*(uint32_t*)&h0, *(uint32_t*)&h1);
        ((uint2*)g_Xh)[i] = p;
    } else {
        __shared__ float t[32][33];
        int idx = blockIdx.x - XCVT_BLOCKS;       // 0..575
        int bx = (idx % (TOKD / 32)) * 32;
        int by = (idx / (TOKD / 32)) * 32;
        int tx = threadIdx.x & 31, ty = threadIdx.x >> 5;  // 32 x 8
#pragma unroll
        for (int i = 0; i < 32; i += 8)
            t[ty + i][tx] = W[(size_t)(by + ty + i) * TOKD + bx + tx];
        __syncthreads();
#pragma unroll
        for (int i = 0; i < 32; i += 8)
            g_Wth[(size_t)(bx + ty + i) * TOKD + by + tx] = __float2half(t[tx][ty + i]);
    }
}

// ---------------- token attention logits via mma.sync fp16 -----------------
#define KCH 32
#define NCHUNK (TOKD / KCH)   // 24
#define LDH 40                // smem row stride in halves (32 + 8 pad = 80B)

__device__ __forceinline__ void issue_chunk(int row0, int col0, int c,
                                            __half* Asm, __half* Bsm, int tid) {
    int k0 = c * KCH;
#pragma unroll
    for (int i = 0; i < 2; i++) {
        int f = tid + i * 256;              // 0..511
        int rr = f >> 2;                    // 0..127
        int seg = (f & 3) * 8;              // 0,8,16,24 halves
        cp16(smem_u32(Asm + rr * LDH + seg),
             g_Xh + (size_t)(row0 + rr) * TOKD + k0 + seg);
        cp16(smem_u32(Bsm + rr * LDH + seg),
             g_Wth + (size_t)(col0 + rr) * TOKD + k0 + seg);
    }
    asm volatile("cp.async.commit_group;" ::: "memory");
}

__global__ void __launch_bounds__(256, 2)
tok_gemm_fp16(const float* __restrict__ tokb,
              const float* __restrict__ tokv) {
    __shared__ __half As[2][128 * LDH];
    __shared__ __half Bs[2][128 * LDH];

    int tid = threadIdx.x;
    int wid = tid >> 5, lane = tid & 31;
    int gid = lane >> 2, tig = lane & 3;
    int warpM = wid >> 1, warpN = wid & 1;
    int row0 = blockIdx.x * 128, col0 = blockIdx.y * 128;

    float acc[2][8][4];
#pragma unroll
    for (int mi = 0; mi < 2; mi++)
#pragma unroll
        for (int nj = 0; nj < 8; nj++)
#pragma unroll
            for (int q = 0; q < 4; q++) acc[mi][nj][q] = 0.f;

    issue_chunk(row0, col0, 0, As[0], Bs[0], tid);

    for (int c = 0; c < NCHUNK; c++) {
        if (c + 1 < NCHUNK) {
            issue_chunk(row0, col0, c + 1, As[(c + 1) & 1], Bs[(c + 1) & 1], tid);
            asm volatile("cp.async.wait_group 1;" ::: "memory");
        } else {
            asm volatile("cp.async.wait_group 0;" ::: "memory");
        }
        __syncthreads();

        const __half* Ab = As[c & 1];
        const __half* Bb = Bs[c & 1];
#pragma unroll
        for (int ks = 0; ks < 2; ks++) {
            int kh = ks * 16 + 2 * tig;
            uint32_t a[2][4];
#pragma unroll
            for (int mi = 0; mi < 2; mi++) {
                int rb = warpM * 32 + mi * 16 + gid;
                a[mi][0] = *(const uint32_t*)(Ab + rb * LDH + kh);
                a[mi][1] = *(const uint32_t*)(Ab + (rb + 8) * LDH + kh);
                a[mi][2] = *(const uint32_t*)(Ab + rb * LDH + kh + 8);
                a[mi][3] = *(const uint32_t*)(Ab + (rb + 8) * LDH + kh + 8);
            }
#pragma unroll
            for (int nj = 0; nj < 8; nj++) {
                int nb = warpN * 64 + nj * 8 + gid;
                uint32_t b0 = *(const uint32_t*)(Bb + nb * LDH + kh);
                uint32_t b1 = *(const uint32_t*)(Bb + nb * LDH + kh + 8);
                mma16(acc[0][nj], a[0], b0, b1);
                mma16(acc[1][nj], a[1], b0, b1);
            }
        }
        __syncthreads();
    }

    // epilogue: per-(col-tile, warpN) partial row sums, no atomics
    float rsum[2][2] = {{0.f, 0.f}, {0.f, 0.f}};
#pragma unroll
    for (int mi = 0; mi < 2; mi++) {
#pragma unroll
        for (int nj = 0; nj < 8; nj++) {
            int n0 = col0 + warpN * 64 + nj * 8 + 2 * tig;
            float bb0 = __ldg(&tokb[n0]), bb1 = __ldg(&tokb[n0 + 1]);
            float vv0 = __ldg(&tokv[n0]), vv1 = __ldg(&tokv[n0 + 1]);
            rsum[mi][0] += tanhf(acc[mi][nj][0] + bb0) * vv0
                         + tanhf(acc[mi][nj][1] + bb1) * vv1;
            rsum[mi][1] += tanhf(acc[mi][nj][2] + bb0) * vv0
                         + tanhf(acc[mi][nj][3] + bb1) * vv1;
        }
    }
    int slot = blockIdx.y * 2 + warpN;   // 0..11
#pragma unroll
    for (int mi = 0; mi < 2; mi++)
#pragma unroll
        for (int h = 0; h < 2; h++) {
            float s = rsum[mi][h];
            s += __shfl_xor_sync(0xffffffffu, s, 1);
            s += __shfl_xor_sync(0xffffffffu, s, 2);
            if (tig == 0)
                g_e_part[slot * MROWS + row0 + warpM * 32 + mi * 16 + h * 8 + gid] = s;
        }
}

// ---------------- tok_pool: fused masked softmax + pooling (fp16 X) --------
__global__ void tok_pool_kernel(const int* __restrict__ ctx_tok) {
    int b = blockIdx.x;
    int dc = blockIdx.y;     // 0..2
    int tid = threadIdx.x;   // 0..255
    __shared__ float red[SEQL];
    __shared__ float a[SEQL];
    __shared__ float2 part[128];

    int row = b * SEQL + tid;
    float ev = 0.f;
#pragma unroll
    for (int j = 0; j < 12; j++) ev += g_e_part[j * MROWS + row];
    float val = (ctx_tok[row] != 0) ? ev : -1e9f;

    red[tid] = val;
    __syncthreads();
    for (int s = 128; s > 0; s >>= 1) {
        if (tid < s) red[tid] = fmaxf(red[tid], red[tid + s]);
        __syncthreads();
    }
    float mx = red[0];
    __syncthreads();
    float ex = expf(val - mx);
    red[tid] = ex;
    __syncthreads();
    for (int s = 128; s > 0; s >>= 1) {
        if (tid < s) red[tid] += red[tid + s];
        __syncthreads();
    }
    a[tid] = ex / red[0];
    __syncthreads();

    int h2 = tid & 127;
    int sh = tid >> 7;       // sequence half
    const __half2* xp = (const __half2*)(g_Xh + (size_t)b * SEQL * TOKD)
                        + dc * 128 + h2 + (size_t)(sh * 128) * (TOKD / 2);
    const float* ap = a + sh * 128;
    const int strid = TOKD / 2;
    float s0 = 0.f, s1 = 0.f, s2 = 0.f, s3 = 0.f;
#pragma unroll 4
    for (int l = 0; l < 128; l += 2) {
        float2 f0 = __half22float2(xp[(size_t)l * strid]);
        float2 f1 = __half22float2(xp[(size_t)(l + 1) * strid]);
        s0 += ap[l] * f0.x;  s1 += ap[l] * f0.y;
        s2 += ap[l + 1] * f1.x;  s3 += ap[l + 1] * f1.y;
    }
    float2 mine = make_float2(s0 + s2, s1 + s3);
    if (sh == 1) part[h2] = mine;
    __syncthreads();
    if (sh == 0) {
        float2 other = part[h2];
        float2 outv = make_float2(mine.x + other.x, mine.y + other.y);
        *(float2*)(g_pool + b * TOKD + dc * 256 + h2 * 2) = outv;
    }
}

// ---------------- gate: ent softmax+combine, linear, gate, user (256 thr) --
__global__ void gate_kernel(const int* __restrict__ ctx_ent,
                            const float* __restrict__ linW,
                            const float* __restrict__ linb,
                            const float* __restrict__ gateW,
                            const float* __restrict__ gateb) {
    int b = blockIdx.x;
    int tid = threadIdx.x;   // 0..255 (8 warps)
    int wid = tid >> 5, lane = tid & 31;
    __shared__ float pool[TOKD];
    __shared__ float cat[2 * KGD];   // [tokr | entr]
    __shared__ int ids[NCTX];
    __shared__ float aw[NCTX];

    for (int i = tid; i < TOKD; i += 256) pool[i] = g_pool[b * TOKD + i];
    if (tid < NCTX) ids[tid] = __ldg(&ctx_ent[b * NCTX + tid]);
    __syncthreads();

    if (tid == 0) {
        float mx = -1e30f;
        float eb[NCTX];
        for (int l = 0; l < NCTX; l++) {
            float v = (ids[l] != 0) ? g_ebuf[b * NCTX + l] : -1e9f;
            eb[l] = v;
            mx = fmaxf(mx, v);
        }
        float sum = 0.f;
        for (int l = 0; l < NCTX; l++) { aw[l] = expf(eb[l] - mx); sum += aw[l]; }
        float inv = 1.0f / sum;
        for (int l = 0; l < NCTX; l++) aw[l] *= inv;
    }
    __syncthreads();

    if (tid < KGD) {
        float er = 0.f;
        for (int l = 0; l < NCTX; l++)
            er += aw[l] * g_kg[(size_t)ids[l] * KGD + tid];
        cat[KGD + tid] = er;
    }
    __syncthreads();

    // tokr: each of 8 warps computes 16 outputs, lane-coalesced float4 reads
    for (int o = wid * 16; o < wid * 16 + 16; o++) {
        const float4* wp = (const float4*)(linW + (size_t)o * TOKD);
        float s = 0.f;
#pragma unroll
        for (int d4 = lane; d4 < TOKD / 4; d4 += 32) {
            float4 w4 = wp[d4];
            float4 p4 = *(const float4*)&pool[d4 * 4];
            s += w4.x * p4.x + w4.y * p4.y + w4.z * p4.z + w4.w * p4.w;
        }
#pragma unroll
        for (int off = 16; off > 0; off >>= 1) s += __shfl_down_sync(0xffffffffu, s, off);
        if (lane == 0) cat[o] = s + linb[o];
    }
    __syncthreads();

    // gate + user: each warp 16 outputs
    for (int o = wid * 16; o < wid * 16 + 16; o++) {
        const float4* gw = (const float4*)(gateW + (size_t)o * (2 * KGD));
        float s = 0.f;
#pragma unroll
        for (int k4 = lane; k4 < (2 * KGD) / 4; k4 += 32) {
            float4 w4 = gw[k4];
            float4 c4 = *(const float4*)&cat[k4 * 4];
            s += w4.x * c4.x + w4.y * c4.y + w4.z * c4.z + w4.w * c4.w;
        }
#pragma unroll
        for (int off = 16; off > 0; off >>= 1) s += __shfl_down_sync(0xffffffffu, s, off);
        if (lane == 0) {
            float g = 1.0f / (1.0f + expf(-(s + gateb[o])));
            g_user[b * KGD + o] = g * cat[o] + (1.0f - g) * cat[KGD + o];
        }
    }
}

// ---------------- scores = user @ kg^T --------------------------------------
__global__ void scores_kernel(float* __restrict__ out) {
    __shared__ float U[BATCH * KGD];
    int tid = threadIdx.x;
    for (int i = tid; i < BATCH * KGD; i += 256) U[i] = g_user[i];
    __syncthreads();

    int n = blockIdx.x * 256 + tid;
    if (n >= N_ENT) return;

    float acc[BATCH];
#pragma unroll
    for (int b = 0; b < BATCH; b++) acc[b] = 0.f;

    const float4* kgp = (const float4*)(g_kg + (size_t)n * KGD);
#pragma unroll 4
    for (int d4 = 0; d4 < KGD / 4; d4++) {
        float4 kv = kgp[d4];
#pragma unroll
        for (int b = 0; b < BATCH; b++) {
            float4 uv = *(const float4*)&U[b * KGD + d4 * 4];
            acc[b] += kv.x * uv.x + kv.y * uv.y + kv.z * uv.z + kv.w * uv.w;
        }
    }
#pragma unroll
    for (int b = 0; b < BATCH; b++) out[(size_t)b * N_ENT + n] = acc[b];
}

// ---------------- launch ----------------------------------------------------
extern "C" void kernel_launch(void* const* d_in, const int* in_sizes, int n_in,
                              void* d_out, int out_size) {
    const int*   ctx_ent  = (const int*)d_in[0];
    const int*   ctx_tok  = (const int*)d_in[1];
    const int*   edge_idx = (const int*)d_in[2];
    const int*   edge_typ = (const int*)d_in[3];
    const float* tok_emb  = (const float*)d_in[4];
    const float* comp     = (const float*)d_in[5];
    const float* basis    = (const float*)d_in[6];
    const float* root     = (const float*)d_in[7];
    const float* rg_bias  = (const float*)d_in[8];
    const float* entW     = (const float*)d_in[9];
    const float* entb     = (const float*)d_in[10];
    const float* entv     = (const float*)d_in[11];
    const float* tokW     = (const float*)d_in[12];
    const float* tokb     = (const float*)d_in[13];
    const float* tokv     = (const float*)d_in[14];
    const float* linW     = (const float*)d_in[15];
    const float* linb     = (const float*)d_in[16];
    const float* gateW    = (const float*)d_in[17];
    const float* gateb    = (const float*)d_in[18];
    float* out = (float*)d_out;

    cudaFuncSetAttribute(scan_kernel,
                         cudaFuncAttributeMaxDynamicSharedMemorySize,
                         N_ENT * (int)sizeof(int));

    void *p_cnt = nullptr, *p_deg = nullptr, *p_pos = nullptr;
    cudaGetSymbolAddress(&p_cnt, g_cnt);
    cudaGetSymbolAddress(&p_deg, g_deg);
    cudaGetSymbolAddress(&p_pos, g_pos);

    cudaStream_t s1, s2;
    cudaEvent_t e0, ew, ep;
    cudaStreamCreateWithFlags(&s1, cudaStreamNonBlocking);
    cudaStreamCreateWithFlags(&s2, cudaStreamNonBlocking);
    cudaEventCreateWithFlags(&e0, cudaEventDisableTiming);
    cudaEventCreateWithFlags(&ew, cudaEventDisableTiming);
    cudaEventCreateWithFlags(&ep, cudaEventDisableTiming);

    // fork
    cudaEventRecord(e0, 0);
    cudaStreamWaitEvent(s1, e0, 0);
    cudaStreamWaitEvent(s2, e0, 0);

    // s1: RGCN weight table — kernel submission #1
    weight_kernel<<<(960000 + 255) / 256, 256, 0, s1>>>(comp, basis);    // #1
    cudaEventRecord(ew, s1);

    // main: graph bookkeeping (memsets are not kernels)
    cudaMemsetAsync(p_cnt, 0, N_RELS * N_ENT * sizeof(int), 0);
    cudaMemsetAsync(p_deg, 0, N_ENT * sizeof(int), 0);
    cudaMemsetAsync(p_pos, 0, N_ENT * sizeof(int), 0);
    count_kernel<<<(NEDGE + 255) / 256, 256>>>(edge_idx, edge_typ);      // #2
    scan_kernel<<<1, 1024, N_ENT * sizeof(int)>>>();                     // #3
    place_kernel<<<(NEDGE + 255) / 256, 256>>>(edge_idx, edge_typ);      // #4

    // s2: token path (independent; executes from t=0)
    prep_kernel<<<XCVT_BLOCKS + (TOKD / 32) * (TOKD / 32), 256, 0, s2>>>(tok_emb, tokW); // #5
    tok_gemm_fp16<<<dim3(64, 6), 256, 0, s2>>>(tokb, tokv);              // #6
    tok_pool_kernel<<<dim3(BATCH, 3), 256, 0, s2>>>(ctx_tok);            // #7
    cudaEventRecord(ep, s2);

    // join weight -> aggregate -> ent_logits (all critical path, main stream)
    cudaStreamWaitEvent(0, ew, 0);
    aggregate_kernel<<<(N_ENT * 32 + 255) / 256, 256>>>(root, rg_bias);  // #8
    ent_logits_kernel<<<NCTX, 1024>>>(ctx_ent, entW, entb, entv);        // #9

    // join token path -> gate, scores
    cudaStreamWaitEvent(0, ep, 0);
    gate_kernel<<<BATCH, 256>>>(ctx_ent, linW, linb, gateW, gateb);      // #10
    scores_kernel<<<(N_ENT + 255) / 256, 256>>>(out);                    // #11

    cudaEventDestroy(e0);
    cudaEventDestroy(ew);
    cudaEventDestroy(ep);
    cudaStreamDestroy(s1);
    cudaStreamDestroy(s2);
}